// round 15
// baseline (speedup 1.0000x reference)
#include <cuda_runtime.h>

#define GRIPPER_DEPTH 0.1034f

__global__ void __launch_bounds__(256) contactnet_kernel4(
    const float4* __restrict__ pts4,
    const float4* __restrict__ z14,
    const float4* __restrict__ z24,
    const float4* __restrict__ s4,
    const float4* __restrict__ w4,
    float* __restrict__ out,
    int n)  // n = number of points (multiple of 4)
{
    int t = blockIdx.x * blockDim.x + threadIdx.x;   // handles points [4t, 4t+4)
    int nq = n >> 2;
    if (t >= nq) return;

    // ---- vectorized loads: 3x float4 per vec3 array = 4 points, fully coalesced ----
    float p[12], a[12], b[12];
    {
        float4 v0 = __ldcs(pts4 + 3 * t + 0);
        float4 v1 = __ldcs(pts4 + 3 * t + 1);
        float4 v2 = __ldcs(pts4 + 3 * t + 2);
        *reinterpret_cast<float4*>(p + 0) = v0;
        *reinterpret_cast<float4*>(p + 4) = v1;
        *reinterpret_cast<float4*>(p + 8) = v2;
        // points passthrough: store immediately, same layout
        float4* po = reinterpret_cast<float4*>(out);
        __stcs(po + 3 * t + 0, v0);
        __stcs(po + 3 * t + 1, v1);
        __stcs(po + 3 * t + 2, v2);
    }
    {
        *reinterpret_cast<float4*>(a + 0) = __ldcs(z14 + 3 * t + 0);
        *reinterpret_cast<float4*>(a + 4) = __ldcs(z14 + 3 * t + 1);
        *reinterpret_cast<float4*>(a + 8) = __ldcs(z14 + 3 * t + 2);
    }
    {
        *reinterpret_cast<float4*>(b + 0) = __ldcs(z24 + 3 * t + 0);
        *reinterpret_cast<float4*>(b + 4) = __ldcs(z24 + 3 * t + 1);
        *reinterpret_cast<float4*>(b + 8) = __ldcs(z24 + 3 * t + 2);
    }
    float4 sv = __ldcs(s4 + t);
    float4 wv = __ldcs(w4 + t);
    float svv[4] = {sv.x, sv.y, sv.z, sv.w};
    float wvv[4] = {wv.x, wv.y, wv.z, wv.w};

    // grasp block base for point 4t: out + 3n + 16*(4t)
    float4* g = reinterpret_cast<float4*>(out + (size_t)3 * n + (size_t)64 * t);

#pragma unroll
    for (int k = 0; k < 4; k++) {
        float px = p[3 * k + 0], py = p[3 * k + 1], pz = p[3 * k + 2];
        float ax = a[3 * k + 0], ay = a[3 * k + 1], az = a[3 * k + 2];
        float bx = b[3 * k + 0], by = b[3 * k + 1], bz = b[3 * k + 2];

        // x_col = z1 / ||z1||
        float inv1 = rsqrtf(fmaf(ax, ax, fmaf(ay, ay, az * az)));
        float xx = ax * inv1, xy = ay * inv1, xz = az * inv1;

        // z_col = normalize(z2 - (x.z2) x)   (||z2|| divide cancels under normalize)
        float inner = fmaf(xx, bx, fmaf(xy, by, xz * bz));
        float apx = fmaf(-inner, xx, bx);
        float apy = fmaf(-inner, xy, by);
        float apz = fmaf(-inner, xz, bz);
        float invz = rsqrtf(fmaf(apx, apx, fmaf(apy, apy, apz * apz)));
        float zx = apx * invz, zy = apy * invz, zz = apz * invz;

        // y_col = normalize(cross(z, x))
        float cx = fmaf(zy, xz, -zz * xy);
        float cy = fmaf(zz, xx, -zx * xz);
        float cz = fmaf(zx, xy, -zy * xx);
        float invy = rsqrtf(fmaf(cx, cx, fmaf(cy, cy, cz * cz)));
        float yx = cx * invy, yy = cy * invy, yz = cz * invy;

        // t_col = p + 0.5*w*x - depth*z  (raw w, pre-ReLU)
        float hw = 0.5f * wvv[k];
        float tx = fmaf(hw, xx, fmaf(-GRIPPER_DEPTH, zx, px));
        float ty = fmaf(hw, xy, fmaf(-GRIPPER_DEPTH, zy, py));
        float tz = fmaf(hw, xz, fmaf(-GRIPPER_DEPTH, zz, pz));

        // grasp 4x4 row-major: rows = components; cols = (x, y, z, t); bottom (0,0,0,1)
        __stcs(g + 4 * k + 0, make_float4(xx, yx, zx, tx));
        __stcs(g + 4 * k + 1, make_float4(xy, yy, zy, ty));
        __stcs(g + 4 * k + 2, make_float4(xz, yz, zz, tz));
        __stcs(g + 4 * k + 3, make_float4(0.0f, 0.0f, 0.0f, 1.0f));
    }

    // sigmoid(s) and relu(w), vectorized stores
    float4 so = make_float4(1.0f / (1.0f + expf(-svv[0])),
                            1.0f / (1.0f + expf(-svv[1])),
                            1.0f / (1.0f + expf(-svv[2])),
                            1.0f / (1.0f + expf(-svv[3])));
    float4 wo = make_float4(fmaxf(wvv[0], 0.0f), fmaxf(wvv[1], 0.0f),
                            fmaxf(wvv[2], 0.0f), fmaxf(wvv[3], 0.0f));
    __stcs(reinterpret_cast<float4*>(out + (size_t)19 * n) + t, so);
    __stcs(reinterpret_cast<float4*>(out + (size_t)20 * n) + t, wo);
}

extern "C" void kernel_launch(void* const* d_in, const int* in_sizes, int n_in,
                              void* d_out, int out_size) {
    const float4* pts = (const float4*)d_in[0];
    const float4* z1  = (const float4*)d_in[1];
    const float4* z2  = (const float4*)d_in[2];
    const float4* s   = (const float4*)d_in[3];
    const float4* w   = (const float4*)d_in[4];
    float* out = (float*)d_out;

    int n = in_sizes[3];           // element count of s = N points
    int nq = n >> 2;               // threads (4 points each)
    int threads = 256;
    int blocks = (nq + threads - 1) / threads;
    contactnet_kernel4<<<blocks, threads>>>(pts, z1, z2, s, w, out, n);
}

// round 16
// speedup vs baseline: 1.7619x; 1.7619x over previous
#include <cuda_runtime.h>

#define GRIPPER_DEPTH 0.1034f

// 256 threads = 256 points per block. All GMEM traffic is 128-bit coalesced:
// vec3 arrays staged through shared memory (192 float4 loads per array per
// block), then consumed per-thread with a conflict-free stride-3 smem read.
__global__ void __launch_bounds__(256) contactnet_smem(
    const float4* __restrict__ pts4,
    const float4* __restrict__ z14,
    const float4* __restrict__ z24,
    const float4* __restrict__ s4,
    const float4* __restrict__ w4,
    float* __restrict__ out,
    int n)  // n = N points, multiple of 256
{
    __shared__ float sp[768];   // 256 points * 3
    __shared__ float sa[768];
    __shared__ float sb[768];
    __shared__ float sw[256];

    const int tid = threadIdx.x;
    const int blk = blockIdx.x;

    // ---- stage: 192 float4 per vec3 array ----
    if (tid < 192) {
        const int gi = blk * 192 + tid;
        float4 vp = __ldcs(pts4 + gi);
        float4 va = __ldcs(z14 + gi);
        float4 vb = __ldcs(z24 + gi);
        reinterpret_cast<float4*>(sp)[tid] = vp;
        reinterpret_cast<float4*>(sa)[tid] = va;
        reinterpret_cast<float4*>(sb)[tid] = vb;
        // points passthrough straight from registers (same layout)
        __stcs(reinterpret_cast<float4*>(out) + gi, vp);
    }
    // ---- s / w: 64 float4 per block; sigmoid & relu written here ----
    if (tid < 64) {
        const int gi = blk * 64 + tid;
        float4 vs = __ldcs(s4 + gi);
        float4 vw = __ldcs(w4 + gi);
        reinterpret_cast<float4*>(sw)[tid] = vw;
        float4 so = make_float4(1.0f / (1.0f + expf(-vs.x)),
                                1.0f / (1.0f + expf(-vs.y)),
                                1.0f / (1.0f + expf(-vs.z)),
                                1.0f / (1.0f + expf(-vs.w)));
        float4 wo = make_float4(fmaxf(vw.x, 0.0f), fmaxf(vw.y, 0.0f),
                                fmaxf(vw.z, 0.0f), fmaxf(vw.w, 0.0f));
        __stcs(reinterpret_cast<float4*>(out + (size_t)19 * n) + gi, so);
        __stcs(reinterpret_cast<float4*>(out + (size_t)20 * n) + gi, wo);
    }
    __syncthreads();

    // ---- compute: one point per thread ----
    // stride-3 smem reads: bank = (3*lane + c) mod 32, 3 coprime 32 -> conflict-free
    const float px = sp[3 * tid + 0], py = sp[3 * tid + 1], pz = sp[3 * tid + 2];
    const float ax = sa[3 * tid + 0], ay = sa[3 * tid + 1], az = sa[3 * tid + 2];
    const float bx = sb[3 * tid + 0], by = sb[3 * tid + 1], bz = sb[3 * tid + 2];
    const float wv = sw[tid];

    // x_col = z1 / ||z1||
    float inv1 = rsqrtf(fmaf(ax, ax, fmaf(ay, ay, az * az)));
    float xx = ax * inv1, xy = ay * inv1, xz = az * inv1;

    // z_col = normalize(z2 - (x.z2) x)   (||z2|| divide cancels under normalize)
    float inner = fmaf(xx, bx, fmaf(xy, by, xz * bz));
    float apx = fmaf(-inner, xx, bx);
    float apy = fmaf(-inner, xy, by);
    float apz = fmaf(-inner, xz, bz);
    float invz = rsqrtf(fmaf(apx, apx, fmaf(apy, apy, apz * apz)));
    float zx = apx * invz, zy = apy * invz, zz = apz * invz;

    // y_col = normalize(cross(z, x))
    float cx = fmaf(zy, xz, -zz * xy);
    float cy = fmaf(zz, xx, -zx * xz);
    float cz = fmaf(zx, xy, -zy * xx);
    float invy = rsqrtf(fmaf(cx, cx, fmaf(cy, cy, cz * cz)));
    float yx = cx * invy, yy = cy * invy, yz = cz * invy;

    // t_col = p + 0.5*w*x - depth*z  (raw w, pre-ReLU)
    float hw = 0.5f * wv;
    float tx = fmaf(hw, xx, fmaf(-GRIPPER_DEPTH, zx, px));
    float ty = fmaf(hw, xy, fmaf(-GRIPPER_DEPTH, zy, py));
    float tz = fmaf(hw, xz, fmaf(-GRIPPER_DEPTH, zz, pz));

    // grasp 4x4 row-major: rows = components; cols = (x, y, z, t); bottom (0,0,0,1)
    const int i = blk * 256 + tid;
    float4* g = reinterpret_cast<float4*>(out + (size_t)3 * n + (size_t)16 * i);
    __stcs(g + 0, make_float4(xx, yx, zx, tx));
    __stcs(g + 1, make_float4(xy, yy, zy, ty));
    __stcs(g + 2, make_float4(xz, yz, zz, tz));
    __stcs(g + 3, make_float4(0.0f, 0.0f, 0.0f, 1.0f));
}

extern "C" void kernel_launch(void* const* d_in, const int* in_sizes, int n_in,
                              void* d_out, int out_size) {
    const float4* pts = (const float4*)d_in[0];
    const float4* z1  = (const float4*)d_in[1];
    const float4* z2  = (const float4*)d_in[2];
    const float4* s   = (const float4*)d_in[3];
    const float4* w   = (const float4*)d_in[4];
    float* out = (float*)d_out;

    int n = in_sizes[3];            // N points (4,194,304; multiple of 256)
    int blocks = n / 256;           // one block per 256 points
    contactnet_smem<<<blocks, 256>>>(pts, z1, z2, s, w, out, n);
}